// round 16
// baseline (speedup 1.0000x reference)
#include <cuda_runtime.h>
#include <cuda_bf16.h>

#define Bb   8
#define CINc 128
#define COUTc 256
#define Nn   8192
#define Mm   2048
#define Kk   16
#define YSIZE (Bb*COUTc*Mm)          // 4194304
#define FPS_SMEM (3*Nn*4)            // 98304 bytes
#define WS_STRIDE 130
#define GEMM_SMEM ((128*CINc + CINc*WS_STRIDE)*4)  // 132096 bytes

typedef unsigned long long u64;

// ---------- packed f32x2 helpers (exact per-element rn semantics) ----------
// NOTE: PTX f32x2 family is add/mul/fma ONLY — no min/max (R15 compile failure).
__device__ __forceinline__ u64 pk2(float a, float b){ u64 r; asm("mov.b64 %0,{%1,%2};":"=l"(r):"f"(a),"f"(b)); return r; }
__device__ __forceinline__ void upk2(u64 v, float&a, float&b){ asm("mov.b64 {%0,%1},%2;":"=f"(a),"=f"(b):"l"(v)); }
__device__ __forceinline__ u64 add2(u64 a,u64 b){ u64 r; asm("add.rn.f32x2 %0,%1,%2;":"=l"(r):"l"(a),"l"(b)); return r; }
__device__ __forceinline__ u64 mul2(u64 a,u64 b){ u64 r; asm("mul.rn.f32x2 %0,%1,%2;":"=l"(r):"l"(a),"l"(b)); return r; }
__device__ __forceinline__ u64 fma2_(u64 a,u64 b,u64 c){ u64 r; asm("fma.rn.f32x2 %0,%1,%2,%3;":"=l"(r):"l"(a),"l"(b),"l"(c)); return r; }

// ---------- device scratch ----------
__device__ float g_xt[(size_t)Bb*Nn*CINc];     // x transposed to (B,N,CIN)
__device__ float g_pn2[Bb*Nn];                 // |p|^2 per point (fma-chained)
__device__ int   g_knn[Bb*Mm*Kk];              // knn indices
__device__ float g_hmax[(size_t)Bb*Mm*COUTc];
__device__ float g_hmin[(size_t)Bb*Mm*COUTc];
__device__ float g_csum[COUTc], g_csumsq[COUTc];
__device__ float g_scale[COUTc], g_bias[COUTc];
__device__ int   g_selmax[COUTc];

// ---------- K0: transpose x (B,CIN,N) -> (B,N,CIN) ----------
__global__ void k_transpose(const float* __restrict__ x){
    __shared__ float t[32][33];
    int b = blockIdx.z, n0 = blockIdx.x*32, c0 = blockIdx.y*32;
    t[threadIdx.y][threadIdx.x] = x[((size_t)(b*CINc + c0 + threadIdx.y))*Nn + n0 + threadIdx.x];
    __syncthreads();
    g_xt[((size_t)b*Nn + (n0 + threadIdx.y))*CINc + c0 + threadIdx.x] = t[threadIdx.x][threadIdx.y];
}

// ---------- K0b: |p|^2 (FMA-contracted chain) + zero channel accumulators ----------
__global__ void k_prep(const float* __restrict__ coords){
    int i = blockIdx.x*256 + threadIdx.x;      // 0 .. B*N-1
    int b = i / Nn, n = i % Nn;
    float px = coords[(b*3+0)*Nn + n];
    float py = coords[(b*3+1)*Nn + n];
    float pz = coords[(b*3+2)*Nn + n];
    g_pn2[i] = __fmaf_rn(pz, pz, __fmaf_rn(py, py, __fmul_rn(px, px)));
    if (blockIdx.x == 0 && threadIdx.x < COUTc){
        g_csum[threadIdx.x]   = 0.f;
        g_csumsq[threadIdx.x] = 0.f;
    }
}

// ---------- K1: FPS — 1024 thr x 8 pts; value-only fmax tree + deferred index find ----------
__global__ void __launch_bounds__(1024,1) k_fps(const float* __restrict__ coords,
                                                float* __restrict__ out_fps){
    extern __shared__ float sm[];
    float* spx = sm; float* spy = sm + Nn; float* spz = sm + 2*Nn;
    __shared__ u64 skey[3];
    const int b = blockIdx.x, tid = threadIdx.x, lane = tid & 31;
    const float* cb = coords + (size_t)b*3*Nn;
    for (int i = tid; i < Nn; i += 1024){
        spx[i] = cb[i]; spy[i] = cb[Nn+i]; spz[i] = cb[2*Nn+i];
    }
    if (tid == 0){
        skey[0] = 0ull; skey[1] = 0ull; skey[2] = 0ull;
        out_fps[(b*3+0)*Mm] = cb[0];
        out_fps[(b*3+1)*Mm] = cb[Nn];
        out_fps[(b*3+2)*Mm] = cb[2*Nn];
    }
    __syncthreads();

    const int base = tid*8;
    u64 px2[4], py2[4], pz2[4];
    {
        float4 a = *(const float4*)&spx[base]; float4 c = *(const float4*)&spx[base+4];
        px2[0]=pk2(a.x,a.y); px2[1]=pk2(a.z,a.w); px2[2]=pk2(c.x,c.y); px2[3]=pk2(c.z,c.w);
        a = *(const float4*)&spy[base]; c = *(const float4*)&spy[base+4];
        py2[0]=pk2(a.x,a.y); py2[1]=pk2(a.z,a.w); py2[2]=pk2(c.x,c.y); py2[3]=pk2(c.z,c.w);
        a = *(const float4*)&spz[base]; c = *(const float4*)&spz[base+4];
        pz2[0]=pk2(a.x,a.y); pz2[1]=pk2(a.z,a.w); pz2[2]=pk2(c.x,c.y); pz2[3]=pk2(c.z,c.w);
    }
    float mind[8];
    #pragma unroll
    for (int j=0;j<8;j++) mind[j] = 1e10f;

    int cur = 0;
    for (int m = 1; m < Mm; m++){
        // distance update — bit-identical arithmetic to the passing versions
        float lx = spx[cur], ly = spy[cur], lz = spz[cur];
        u64 nlx = pk2(-lx,-lx), nly = pk2(-ly,-ly), nlz = pk2(-lz,-lz);
        #pragma unroll
        for (int j=0;j<4;j++){
            u64 dx = add2(px2[j], nlx);
            u64 dy = add2(py2[j], nly);
            u64 dz = add2(pz2[j], nlz);
            u64 s  = add2(add2(mul2(dx,dx), mul2(dy,dy)), mul2(dz,dz));
            float s0, s1; upk2(s, s0, s1);
            mind[2*j]   = fminf(mind[2*j],   s0);
            mind[2*j+1] = fminf(mind[2*j+1], s1);
        }
        // value-only max tree (no index tracking on the common path)
        float t0 = fmaxf(mind[0],mind[1]), t1 = fmaxf(mind[2],mind[3]);
        float t2 = fmaxf(mind[4],mind[5]), t3 = fmaxf(mind[6],mind[7]);
        float bv = fmaxf(fmaxf(t0,t1), fmaxf(t2,t3));
        // warp argmax on value bits (all values >= 0 so float order == uint order)
        unsigned vb = __float_as_uint(bv);
        unsigned wmax = __reduce_max_sync(0xffffffffu, vb);
        unsigned ball = __ballot_sync(0xffffffffu, vb == wmax);
        if (lane == (__ffs(ball) - 1)){
            // deferred index find: lowest j with mind[j]==bv (descending scan keeps lowest)
            int bestj = 7;
            #pragma unroll
            for (int j = 6; j >= 0; j--) if (mind[j] == bv) bestj = j;
            u64 key = ((u64)wmax << 32) | (unsigned)(~(base + bestj));
            atomicMax(&skey[m % 3], key);
        }
        if (tid == 0) skey[(m + 2) % 3] = 0ull;   // reset 2 iters ahead (no race)
        __syncthreads();
        cur = (int)(~((unsigned)skey[m % 3]));
        if (tid == 0){
            out_fps[(b*3+0)*Mm + m] = spx[cur];
            out_fps[(b*3+1)*Mm + m] = spy[cur];
            out_fps[(b*3+2)*Mm + m] = spz[cur];
        }
    }
}

// ---------- K2: KNN (one warp per query, top-16), 4 points/thread via LDS.128 ----------
#define KNN_TILE 2048
__global__ void __launch_bounds__(256) k_knn(const float* __restrict__ coords,
                                             const float* __restrict__ fps_coords){
    __shared__ __align__(16) float sx[KNN_TILE], sy[KNN_TILE], sz[KNN_TILE], sp2[KNN_TILE];
    const int b = blockIdx.y, tid = threadIdx.x;
    const int warp = tid >> 5, lane = tid & 31;
    const int m = blockIdx.x*8 + warp;

    const float qx = fps_coords[(b*3+0)*Mm + m];
    const float qy = fps_coords[(b*3+1)*Mm + m];
    const float qz = fps_coords[(b*3+2)*Mm + m];
    const float q2 = __fmaf_rn(qz, qz, __fmaf_rn(qy, qy, __fmul_rn(qx, qx)));

    const u64 qx2 = pk2(qx,qx), qy2 = pk2(qy,qy), qz2 = pk2(qz,qz);
    const u64 q22 = pk2(q2,q2), m22 = pk2(-2.0f,-2.0f);

    const float INF = __int_as_float(0x7f800000);
    float cand[Kk]; int candi[Kk];
    #pragma unroll
    for (int j=0;j<Kk;j++){ cand[j] = INF; candi[j] = -1; }

    for (int t = 0; t < Nn; t += KNN_TILE){
        __syncthreads();
        for (int i = tid; i < KNN_TILE; i += 256){
            sx[i]  = coords[(b*3+0)*Nn + t + i];
            sy[i]  = coords[(b*3+1)*Nn + t + i];
            sz[i]  = coords[(b*3+2)*Nn + t + i];
            sp2[i] = g_pn2[b*Nn + t + i];
        }
        __syncthreads();
        for (int i = lane*4; i < KNN_TILE; i += 128){
            float4 ax = *(const float4*)&sx[i];
            float4 ay = *(const float4*)&sy[i];
            float4 az = *(const float4*)&sz[i];
            float4 ap = *(const float4*)&sp2[i];
            u64 sxA = pk2(ax.x,ax.y), sxB = pk2(ax.z,ax.w);
            u64 syA = pk2(ay.x,ay.y), syB = pk2(ay.z,ay.w);
            u64 szA = pk2(az.x,az.y), szB = pk2(az.z,az.w);
            u64 spA = pk2(ap.x,ap.y), spB = pk2(ap.z,ap.w);
            // per-element identical to: d = (q2 + p2) - 2*dot, dot fma-chained
            u64 dotA = fma2_(qz2, szA, fma2_(qy2, syA, mul2(qx2, sxA)));
            u64 dotB = fma2_(qz2, szB, fma2_(qy2, syB, mul2(qx2, sxB)));
            u64 dA   = add2(add2(q22, spA), mul2(m22, dotA));
            u64 dB   = add2(add2(q22, spB), mul2(m22, dotB));
            float d0, d1, d2, d3;
            upk2(dA, d0, d1); upk2(dB, d2, d3);
            #pragma unroll
            for (int e = 0; e < 4; e++){
                float de = (e==0) ? d0 : (e==1) ? d1 : (e==2) ? d2 : d3;
                if (de < cand[Kk-1]){
                    float v = de; int vi = t + i + e;
                    #pragma unroll
                    for (int j=0;j<Kk;j++){
                        if (v < cand[j]){
                            float tv = cand[j]; int ti = candi[j];
                            cand[j] = v; candi[j] = vi; v = tv; vi = ti;
                        }
                    }
                }
            }
        }
    }
    // warp merge: 16 rounds of argmin over per-thread sorted heads
    for (int r = 0; r < Kk; r++){
        float v = cand[0]; int vi = candi[0];
        #pragma unroll
        for (int off=16; off>0; off>>=1){
            float ov = __shfl_xor_sync(0xffffffffu, v, off);
            int   oi = __shfl_xor_sync(0xffffffffu, vi, off);
            if (ov < v || (ov == v && oi < vi)){ v = ov; vi = oi; }
        }
        bool mine = (cand[0] == v && candi[0] == vi);
        if (mine){
            #pragma unroll
            for (int j=0;j<Kk-1;j++){ cand[j] = cand[j+1]; candi[j] = candi[j+1]; }
            cand[Kk-1] = INF; candi[Kk-1] = -1;
        }
        if (lane == 0) g_knn[(b*Mm + m)*Kk + r] = vi;
    }
}

// ---------- K3: gather + GEMM (fp32 via fma.f32x2) + fused K-reduction epilogue ----------
__global__ void __launch_bounds__(256) k_gemm(const float* __restrict__ W){
    extern __shared__ float sm[];
    float* As = sm;                         // [128][CIN] row-major
    float* Ws = sm + 128*CINc;              // [CIN][WS_STRIDE]
    __shared__ float ssum[128], ssq[128];
    const int b = blockIdx.z, mb = blockIdx.x*8, ob = blockIdx.y*128;
    const int tid = threadIdx.x;
    if (tid < 128){ ssum[tid] = 0.f; ssq[tid] = 0.f; }

    for (int i = tid; i < 128*CINc; i += 256){
        int o = i >> 7, c = i & 127;
        Ws[c*WS_STRIDE + o] = W[(ob + o)*CINc + c];
    }
    {
        const int warp = tid >> 5, lane = tid & 31;
        for (int r = warp; r < 128; r += 8){
            int q = r >> 4, k = r & 15;
            int gi = g_knn[(b*Mm + mb + q)*Kk + k];
            const float4* src = (const float4*)&g_xt[((size_t)b*Nn + gi)*CINc];
            ((float4*)&As[r*CINc])[lane] = src[lane];
        }
    }
    __syncthreads();

    const int tx = tid & 15, ty = tid >> 4;
    const int r0 = ty*8, c0 = tx*8;
    u64 acc[8][4];
    #pragma unroll
    for (int j=0;j<8;j++){ acc[j][0]=0ull; acc[j][1]=0ull; acc[j][2]=0ull; acc[j][3]=0ull; }

    #pragma unroll 4
    for (int c = 0; c < CINc; c++){
        u64 w2[4];
        const u64* wp = (const u64*)&Ws[c*WS_STRIDE + c0];
        #pragma unroll
        for (int p=0;p<4;p++) w2[p] = wp[p];
        #pragma unroll
        for (int j=0;j<8;j++){
            float a = As[(r0+j)*CINc + c];
            u64 ad = pk2(a, a);
            #pragma unroll
            for (int p=0;p<4;p++) acc[j][p] = fma2_(ad, w2[p], acc[j][p]);
        }
    }

    float h[8][8];
    #pragma unroll
    for (int j=0;j<8;j++)
        #pragma unroll
        for (int p=0;p<4;p++) upk2(acc[j][p], h[j][2*p], h[j][2*p+1]);

    float mx[8], mn[8], s[8], s2[8];
    #pragma unroll
    for (int cc=0;cc<8;cc++){
        mx[cc] = -__int_as_float(0x7f800000); mn[cc] = __int_as_float(0x7f800000);
        s[cc] = 0.f; s2[cc] = 0.f;
        #pragma unroll
        for (int j=0;j<8;j++){
            float v = h[j][cc];
            mx[cc] = fmaxf(mx[cc], v); mn[cc] = fminf(mn[cc], v);
            s[cc] += v; s2[cc] = fmaf(v, v, s2[cc]);
        }
    }
    const int lane = tid & 31;
    #pragma unroll
    for (int cc=0;cc<8;cc++){
        mx[cc] = fmaxf(mx[cc], __shfl_xor_sync(0xffffffffu, mx[cc], 16));
        mn[cc] = fminf(mn[cc], __shfl_xor_sync(0xffffffffu, mn[cc], 16));
        s[cc]  += __shfl_xor_sync(0xffffffffu, s[cc], 16);
        s2[cc] += __shfl_xor_sync(0xffffffffu, s2[cc], 16);
    }
    if (lane < 16){
        const int q = tid >> 5;
        const size_t rowo = ((size_t)(b*Mm + mb + q))*COUTc + ob + c0;
        #pragma unroll
        for (int cc=0;cc<8;cc++){
            g_hmax[rowo + cc] = mx[cc];
            g_hmin[rowo + cc] = mn[cc];
            atomicAdd(&ssum[c0 + cc], s[cc]);
            atomicAdd(&ssq[c0 + cc],  s2[cc]);
        }
    }
    __syncthreads();
    if (tid < 128){
        atomicAdd(&g_csum[ob + tid],   ssum[tid]);
        atomicAdd(&g_csumsq[ob + tid], ssq[tid]);
    }
}

// ---------- K4: BN coefficients ----------
__global__ void k_finalize(const float* __restrict__ gamma, const float* __restrict__ beta){
    int o = threadIdx.x;
    const float cnt = (float)(Bb*Mm*Kk);
    float mean = g_csum[o] / cnt;
    float var  = g_csumsq[o] / cnt - mean*mean;
    float rs   = rsqrtf(var + 1e-5f);
    float g    = gamma[o];
    float sc   = rs * g;
    g_scale[o]  = sc;
    g_bias[o]   = beta[o] - mean*sc;
    g_selmax[o] = (g >= 0.f) ? 1 : 0;
}

// ---------- K5: normalize + relu + transpose to (B,COUT,M) ----------
__global__ void k_out(float* __restrict__ y){
    __shared__ float t[32][33];
    const int b = blockIdx.z, m0 = blockIdx.x*32, o0 = blockIdx.y*32;
    {
        int o = o0 + threadIdx.x, m = m0 + threadIdx.y;
        size_t idx = ((size_t)(b*Mm + m))*COUTc + o;
        t[threadIdx.y][threadIdx.x] = g_selmax[o] ? g_hmax[idx] : g_hmin[idx];
    }
    __syncthreads();
    {
        int o = o0 + threadIdx.y, m = m0 + threadIdx.x;
        float h = t[threadIdx.x][threadIdx.y];
        y[((size_t)(b*COUTc + o))*Mm + m] = fmaxf(fmaf(h, g_scale[o], g_bias[o]), 0.f);
    }
}

extern "C" void kernel_launch(void* const* d_in, const int* in_sizes, int n_in,
                              void* d_out, int out_size){
    const float* x      = (const float*)d_in[0];
    const float* coords = (const float*)d_in[1];
    const float* W      = (const float*)d_in[2];
    const float* gamma  = (const float*)d_in[3];
    const float* beta   = (const float*)d_in[4];
    float* out = (float*)d_out;
    float* out_fps = out + YSIZE;

    cudaFuncSetAttribute(k_fps,  cudaFuncAttributeMaxDynamicSharedMemorySize, FPS_SMEM);
    cudaFuncSetAttribute(k_gemm, cudaFuncAttributeMaxDynamicSharedMemorySize, GEMM_SMEM);

    k_transpose<<<dim3(Nn/32, CINc/32, Bb), dim3(32,32)>>>(x);
    k_prep<<<(Bb*Nn)/256, 256>>>(coords);
    k_fps<<<Bb, 1024, FPS_SMEM>>>(coords, out_fps);
    k_knn<<<dim3(Mm/8, Bb), 256>>>(coords, out_fps);
    k_gemm<<<dim3(Mm/8, COUTc/128, Bb), 256, GEMM_SMEM>>>(W);
    k_finalize<<<1, COUTc>>>(gamma, beta);
    k_out<<<dim3(Mm/32, COUTc/32, Bb), dim3(32,32)>>>(out);
}

// round 17
// speedup vs baseline: 1.1323x; 1.1323x over previous
#include <cuda_runtime.h>
#include <cuda_bf16.h>

#define Bb   8
#define CINc 128
#define COUTc 256
#define Nn   8192
#define Mm   2048
#define Kk   16
#define YSIZE (Bb*COUTc*Mm)          // 4194304
#define FPS_SMEM (3*Nn*4)            // 98304 bytes
#define WS_STRIDE 130
#define GEMM_SMEM ((128*CINc + CINc*WS_STRIDE)*4)  // 132096 bytes

typedef unsigned long long u64;

// ---------- packed f32x2 helpers (exact per-element rn semantics) ----------
// NOTE: PTX f32x2 family is add/mul/fma ONLY — no min/max.
__device__ __forceinline__ u64 pk2(float a, float b){ u64 r; asm("mov.b64 %0,{%1,%2};":"=l"(r):"f"(a),"f"(b)); return r; }
__device__ __forceinline__ void upk2(u64 v, float&a, float&b){ asm("mov.b64 {%0,%1},%2;":"=f"(a),"=f"(b):"l"(v)); }
__device__ __forceinline__ u64 add2(u64 a,u64 b){ u64 r; asm("add.rn.f32x2 %0,%1,%2;":"=l"(r):"l"(a),"l"(b)); return r; }
__device__ __forceinline__ u64 mul2(u64 a,u64 b){ u64 r; asm("mul.rn.f32x2 %0,%1,%2;":"=l"(r):"l"(a),"l"(b)); return r; }
__device__ __forceinline__ u64 fma2_(u64 a,u64 b,u64 c){ u64 r; asm("fma.rn.f32x2 %0,%1,%2,%3;":"=l"(r):"l"(a),"l"(b),"l"(c)); return r; }

// ---------- device scratch ----------
__device__ float g_xt[(size_t)Bb*Nn*CINc];     // x transposed to (B,N,CIN)
__device__ float g_pn2[Bb*Nn];                 // |p|^2 per point (fma-chained)
__device__ int   g_knn[Bb*Mm*Kk];              // knn indices
__device__ float g_hmax[(size_t)Bb*Mm*COUTc];
__device__ float g_hmin[(size_t)Bb*Mm*COUTc];
__device__ float g_csum[COUTc], g_csumsq[COUTc];
__device__ float g_scale[COUTc], g_bias[COUTc];
__device__ int   g_selmax[COUTc];

// ---------- K0: transpose x (B,CIN,N) -> (B,N,CIN) ----------
__global__ void k_transpose(const float* __restrict__ x){
    __shared__ float t[32][33];
    int b = blockIdx.z, n0 = blockIdx.x*32, c0 = blockIdx.y*32;
    t[threadIdx.y][threadIdx.x] = x[((size_t)(b*CINc + c0 + threadIdx.y))*Nn + n0 + threadIdx.x];
    __syncthreads();
    g_xt[((size_t)b*Nn + (n0 + threadIdx.y))*CINc + c0 + threadIdx.x] = t[threadIdx.x][threadIdx.y];
}

// ---------- K0b: |p|^2 (FMA-contracted chain) + zero channel accumulators ----------
__global__ void k_prep(const float* __restrict__ coords){
    int i = blockIdx.x*256 + threadIdx.x;      // 0 .. B*N-1
    int b = i / Nn, n = i % Nn;
    float px = coords[(b*3+0)*Nn + n];
    float py = coords[(b*3+1)*Nn + n];
    float pz = coords[(b*3+2)*Nn + n];
    g_pn2[i] = __fmaf_rn(pz, pz, __fmaf_rn(py, py, __fmul_rn(px, px)));
    if (blockIdx.x == 0 && threadIdx.x < COUTc){
        g_csum[threadIdx.x]   = 0.f;
        g_csumsq[threadIdx.x] = 0.f;
    }
}

// ---------- K1: FPS — 1024 thr x 8 pts; per-warp slots + dual-redux combine (no atomics) ----------
__global__ void __launch_bounds__(1024,1) k_fps(const float* __restrict__ coords,
                                                float* __restrict__ out_fps){
    extern __shared__ float sm[];
    float* spx = sm; float* spy = sm + Nn; float* spz = sm + 2*Nn;
    __shared__ u64 slots[32];
    const int b = blockIdx.x, tid = threadIdx.x, lane = tid & 31, warp = tid >> 5;
    const float* cb = coords + (size_t)b*3*Nn;
    for (int i = tid; i < Nn; i += 1024){
        spx[i] = cb[i]; spy[i] = cb[Nn+i]; spz[i] = cb[2*Nn+i];
    }
    if (tid == 0){
        out_fps[(b*3+0)*Mm] = cb[0];
        out_fps[(b*3+1)*Mm] = cb[Nn];
        out_fps[(b*3+2)*Mm] = cb[2*Nn];
    }
    __syncthreads();

    const int base = tid*8;
    u64 px2[4], py2[4], pz2[4];
    {
        float4 a = *(const float4*)&spx[base]; float4 c = *(const float4*)&spx[base+4];
        px2[0]=pk2(a.x,a.y); px2[1]=pk2(a.z,a.w); px2[2]=pk2(c.x,c.y); px2[3]=pk2(c.z,c.w);
        a = *(const float4*)&spy[base]; c = *(const float4*)&spy[base+4];
        py2[0]=pk2(a.x,a.y); py2[1]=pk2(a.z,a.w); py2[2]=pk2(c.x,c.y); py2[3]=pk2(c.z,c.w);
        a = *(const float4*)&spz[base]; c = *(const float4*)&spz[base+4];
        pz2[0]=pk2(a.x,a.y); pz2[1]=pk2(a.z,a.w); pz2[2]=pk2(c.x,c.y); pz2[3]=pk2(c.z,c.w);
    }
    float mind[8];
    #pragma unroll
    for (int j=0;j<8;j++) mind[j] = 1e10f;

    int cur = 0;
    for (int m = 1; m < Mm; m++){
        // distance update — bit-identical arithmetic to the passing versions
        float lx = spx[cur], ly = spy[cur], lz = spz[cur];
        u64 nlx = pk2(-lx,-lx), nly = pk2(-ly,-ly), nlz = pk2(-lz,-lz);
        #pragma unroll
        for (int j=0;j<4;j++){
            u64 dx = add2(px2[j], nlx);
            u64 dy = add2(py2[j], nly);
            u64 dz = add2(pz2[j], nlz);
            u64 s  = add2(add2(mul2(dx,dx), mul2(dy,dy)), mul2(dz,dz));
            float s0, s1; upk2(s, s0, s1);
            mind[2*j]   = fminf(mind[2*j],   s0);
            mind[2*j+1] = fminf(mind[2*j+1], s1);
        }
        // local argmax: strict > keeps lowest index on ties (measured-best form)
        float bestv = mind[0]; int bestj = 0;
        #pragma unroll
        for (int j=1;j<8;j++){ if (mind[j] > bestv){ bestv = mind[j]; bestj = j; } }
        // warp argmax: distances >= 0 so float order == uint order
        unsigned vb = __float_as_uint(bestv);
        unsigned wmax = __reduce_max_sync(0xffffffffu, vb);
        unsigned ball = __ballot_sync(0xffffffffu, vb == wmax);
        if (lane == (__ffs(ball) - 1)){
            slots[warp] = ((u64)wmax << 32) | (unsigned)(~(base + bestj));  // plain STS, distinct slot
        }
        __syncthreads();
        // every warp redundantly reduces the 32 per-warp keys (no 2nd barrier, no atomics)
        {
            u64 k = slots[lane];
            unsigned hi = (unsigned)(k >> 32), lo = (unsigned)k;
            unsigned mhi = __reduce_max_sync(0xffffffffu, hi);
            unsigned mlo = __reduce_max_sync(0xffffffffu, (hi == mhi) ? lo : 0u);
            cur = (int)(~mlo);   // lo = ~idx, so max lo == lowest idx among value ties
        }
        if (tid == 0){
            out_fps[(b*3+0)*Mm + m] = spx[cur];
            out_fps[(b*3+1)*Mm + m] = spy[cur];
            out_fps[(b*3+2)*Mm + m] = spz[cur];
        }
    }
}

// ---------- K2: KNN (one warp per query, top-16), 4 points/thread via LDS.128 ----------
#define KNN_TILE 2048
__global__ void __launch_bounds__(256) k_knn(const float* __restrict__ coords,
                                             const float* __restrict__ fps_coords){
    __shared__ __align__(16) float sx[KNN_TILE], sy[KNN_TILE], sz[KNN_TILE], sp2[KNN_TILE];
    const int b = blockIdx.y, tid = threadIdx.x;
    const int warp = tid >> 5, lane = tid & 31;
    const int m = blockIdx.x*8 + warp;

    const float qx = fps_coords[(b*3+0)*Mm + m];
    const float qy = fps_coords[(b*3+1)*Mm + m];
    const float qz = fps_coords[(b*3+2)*Mm + m];
    const float q2 = __fmaf_rn(qz, qz, __fmaf_rn(qy, qy, __fmul_rn(qx, qx)));

    const u64 qx2 = pk2(qx,qx), qy2 = pk2(qy,qy), qz2 = pk2(qz,qz);
    const u64 q22 = pk2(q2,q2), m22 = pk2(-2.0f,-2.0f);

    const float INF = __int_as_float(0x7f800000);
    float cand[Kk]; int candi[Kk];
    #pragma unroll
    for (int j=0;j<Kk;j++){ cand[j] = INF; candi[j] = -1; }

    for (int t = 0; t < Nn; t += KNN_TILE){
        __syncthreads();
        for (int i = tid; i < KNN_TILE; i += 256){
            sx[i]  = coords[(b*3+0)*Nn + t + i];
            sy[i]  = coords[(b*3+1)*Nn + t + i];
            sz[i]  = coords[(b*3+2)*Nn + t + i];
            sp2[i] = g_pn2[b*Nn + t + i];
        }
        __syncthreads();
        for (int i = lane*4; i < KNN_TILE; i += 128){
            float4 ax = *(const float4*)&sx[i];
            float4 ay = *(const float4*)&sy[i];
            float4 az = *(const float4*)&sz[i];
            float4 ap = *(const float4*)&sp2[i];
            u64 sxA = pk2(ax.x,ax.y), sxB = pk2(ax.z,ax.w);
            u64 syA = pk2(ay.x,ay.y), syB = pk2(ay.z,ay.w);
            u64 szA = pk2(az.x,az.y), szB = pk2(az.z,az.w);
            u64 spA = pk2(ap.x,ap.y), spB = pk2(ap.z,ap.w);
            // per-element identical to: d = (q2 + p2) - 2*dot, dot fma-chained
            u64 dotA = fma2_(qz2, szA, fma2_(qy2, syA, mul2(qx2, sxA)));
            u64 dotB = fma2_(qz2, szB, fma2_(qy2, syB, mul2(qx2, sxB)));
            u64 dA   = add2(add2(q22, spA), mul2(m22, dotA));
            u64 dB   = add2(add2(q22, spB), mul2(m22, dotB));
            float d0, d1, d2, d3;
            upk2(dA, d0, d1); upk2(dB, d2, d3);
            #pragma unroll
            for (int e = 0; e < 4; e++){
                float de = (e==0) ? d0 : (e==1) ? d1 : (e==2) ? d2 : d3;
                if (de < cand[Kk-1]){
                    float v = de; int vi = t + i + e;
                    #pragma unroll
                    for (int j=0;j<Kk;j++){
                        if (v < cand[j]){
                            float tv = cand[j]; int ti = candi[j];
                            cand[j] = v; candi[j] = vi; v = tv; vi = ti;
                        }
                    }
                }
            }
        }
    }
    // warp merge: 16 rounds of argmin over per-thread sorted heads
    for (int r = 0; r < Kk; r++){
        float v = cand[0]; int vi = candi[0];
        #pragma unroll
        for (int off=16; off>0; off>>=1){
            float ov = __shfl_xor_sync(0xffffffffu, v, off);
            int   oi = __shfl_xor_sync(0xffffffffu, vi, off);
            if (ov < v || (ov == v && oi < vi)){ v = ov; vi = oi; }
        }
        bool mine = (cand[0] == v && candi[0] == vi);
        if (mine){
            #pragma unroll
            for (int j=0;j<Kk-1;j++){ cand[j] = cand[j+1]; candi[j] = candi[j+1]; }
            cand[Kk-1] = INF; candi[Kk-1] = -1;
        }
        if (lane == 0) g_knn[(b*Mm + m)*Kk + r] = vi;
    }
}

// ---------- K3: gather + GEMM (fp32 via fma.f32x2) + fused K-reduction epilogue ----------
__global__ void __launch_bounds__(256) k_gemm(const float* __restrict__ W){
    extern __shared__ float sm[];
    float* As = sm;                         // [128][CIN] row-major
    float* Ws = sm + 128*CINc;              // [CIN][WS_STRIDE]
    __shared__ float ssum[128], ssq[128];
    const int b = blockIdx.z, mb = blockIdx.x*8, ob = blockIdx.y*128;
    const int tid = threadIdx.x;
    if (tid < 128){ ssum[tid] = 0.f; ssq[tid] = 0.f; }

    for (int i = tid; i < 128*CINc; i += 256){
        int o = i >> 7, c = i & 127;
        Ws[c*WS_STRIDE + o] = W[(ob + o)*CINc + c];
    }
    {
        const int warp = tid >> 5, lane = tid & 31;
        for (int r = warp; r < 128; r += 8){
            int q = r >> 4, k = r & 15;
            int gi = g_knn[(b*Mm + mb + q)*Kk + k];
            const float4* src = (const float4*)&g_xt[((size_t)b*Nn + gi)*CINc];
            ((float4*)&As[r*CINc])[lane] = src[lane];
        }
    }
    __syncthreads();

    const int tx = tid & 15, ty = tid >> 4;
    const int r0 = ty*8, c0 = tx*8;
    u64 acc[8][4];
    #pragma unroll
    for (int j=0;j<8;j++){ acc[j][0]=0ull; acc[j][1]=0ull; acc[j][2]=0ull; acc[j][3]=0ull; }

    #pragma unroll 4
    for (int c = 0; c < CINc; c++){
        u64 w2[4];
        const u64* wp = (const u64*)&Ws[c*WS_STRIDE + c0];
        #pragma unroll
        for (int p=0;p<4;p++) w2[p] = wp[p];
        #pragma unroll
        for (int j=0;j<8;j++){
            float a = As[(r0+j)*CINc + c];
            u64 ad = pk2(a, a);
            #pragma unroll
            for (int p=0;p<4;p++) acc[j][p] = fma2_(ad, w2[p], acc[j][p]);
        }
    }

    float h[8][8];
    #pragma unroll
    for (int j=0;j<8;j++)
        #pragma unroll
        for (int p=0;p<4;p++) upk2(acc[j][p], h[j][2*p], h[j][2*p+1]);

    float mx[8], mn[8], s[8], s2[8];
    #pragma unroll
    for (int cc=0;cc<8;cc++){
        mx[cc] = -__int_as_float(0x7f800000); mn[cc] = __int_as_float(0x7f800000);
        s[cc] = 0.f; s2[cc] = 0.f;
        #pragma unroll
        for (int j=0;j<8;j++){
            float v = h[j][cc];
            mx[cc] = fmaxf(mx[cc], v); mn[cc] = fminf(mn[cc], v);
            s[cc] += v; s2[cc] = fmaf(v, v, s2[cc]);
        }
    }
    const int lane = tid & 31;
    #pragma unroll
    for (int cc=0;cc<8;cc++){
        mx[cc] = fmaxf(mx[cc], __shfl_xor_sync(0xffffffffu, mx[cc], 16));
        mn[cc] = fminf(mn[cc], __shfl_xor_sync(0xffffffffu, mn[cc], 16));
        s[cc]  += __shfl_xor_sync(0xffffffffu, s[cc], 16);
        s2[cc] += __shfl_xor_sync(0xffffffffu, s2[cc], 16);
    }
    if (lane < 16){
        const int q = tid >> 5;
        const size_t rowo = ((size_t)(b*Mm + mb + q))*COUTc + ob + c0;
        #pragma unroll
        for (int cc=0;cc<8;cc++){
            g_hmax[rowo + cc] = mx[cc];
            g_hmin[rowo + cc] = mn[cc];
            atomicAdd(&ssum[c0 + cc], s[cc]);
            atomicAdd(&ssq[c0 + cc],  s2[cc]);
        }
    }
    __syncthreads();
    if (tid < 128){
        atomicAdd(&g_csum[ob + tid],   ssum[tid]);
        atomicAdd(&g_csumsq[ob + tid], ssq[tid]);
    }
}

// ---------- K4: BN coefficients ----------
__global__ void k_finalize(const float* __restrict__ gamma, const float* __restrict__ beta){
    int o = threadIdx.x;
    const float cnt = (float)(Bb*Mm*Kk);
    float mean = g_csum[o] / cnt;
    float var  = g_csumsq[o] / cnt - mean*mean;
    float rs   = rsqrtf(var + 1e-5f);
    float g    = gamma[o];
    float sc   = rs * g;
    g_scale[o]  = sc;
    g_bias[o]   = beta[o] - mean*sc;
    g_selmax[o] = (g >= 0.f) ? 1 : 0;
}

// ---------- K5: normalize + relu + transpose to (B,COUT,M) ----------
__global__ void k_out(float* __restrict__ y){
    __shared__ float t[32][33];
    const int b = blockIdx.z, m0 = blockIdx.x*32, o0 = blockIdx.y*32;
    {
        int o = o0 + threadIdx.x, m = m0 + threadIdx.y;
        size_t idx = ((size_t)(b*Mm + m))*COUTc + o;
        t[threadIdx.y][threadIdx.x] = g_selmax[o] ? g_hmax[idx] : g_hmin[idx];
    }
    __syncthreads();
    {
        int o = o0 + threadIdx.y, m = m0 + threadIdx.x;
        float h = t[threadIdx.x][threadIdx.y];
        y[((size_t)(b*COUTc + o))*Mm + m] = fmaxf(fmaf(h, g_scale[o], g_bias[o]), 0.f);
    }
}

extern "C" void kernel_launch(void* const* d_in, const int* in_sizes, int n_in,
                              void* d_out, int out_size){
    const float* x      = (const float*)d_in[0];
    const float* coords = (const float*)d_in[1];
    const float* W      = (const float*)d_in[2];
    const float* gamma  = (const float*)d_in[3];
    const float* beta   = (const float*)d_in[4];
    float* out = (float*)d_out;
    float* out_fps = out + YSIZE;

    cudaFuncSetAttribute(k_fps,  cudaFuncAttributeMaxDynamicSharedMemorySize, FPS_SMEM);
    cudaFuncSetAttribute(k_gemm, cudaFuncAttributeMaxDynamicSharedMemorySize, GEMM_SMEM);

    k_transpose<<<dim3(Nn/32, CINc/32, Bb), dim3(32,32)>>>(x);
    k_prep<<<(Bb*Nn)/256, 256>>>(coords);
    k_fps<<<Bb, 1024, FPS_SMEM>>>(coords, out_fps);
    k_knn<<<dim3(Mm/8, Bb), 256>>>(coords, out_fps);
    k_gemm<<<dim3(Mm/8, COUTc/128, Bb), 256, GEMM_SMEM>>>(W);
    k_finalize<<<1, COUTc>>>(gamma, beta);
    k_out<<<dim3(Mm/32, COUTc/32, Bb), dim3(32,32)>>>(out);
}